// round 16
// baseline (speedup 1.0000x reference)
#include <cuda_runtime.h>
#include <cstdint>

// ===========================================================================
// NNUE eval via tensor-core mma.sync (tf32, m16n8k8), compute_103-safe PTX.
// R16 = R14 (148 CTAs x 256 thr, warp-private 32 samples, BX overlay region,
// split mid-L1 white/black prefetch) + explicit double-buffered operand
// pipelines in L1/L2 (load step s+1's B-frags + A-ops before step s's MMAs).
// b0/b1/W2 epilogue vectors read from smem (register budget for the buffers).
// ===========================================================================

__device__ __forceinline__ uint32_t f2tf32(float f) {
    uint32_t r; asm("cvt.rna.tf32.f32 %0, %1;" : "=r"(r) : "f"(f)); return r;
}

__device__ __forceinline__ void mma8(float* d,
                                     uint32_t a0, uint32_t a1, uint32_t a2, uint32_t a3,
                                     uint32_t b0, uint32_t b1) {
    asm volatile(
        "mma.sync.aligned.m16n8k8.row.col.f32.tf32.tf32.f32 "
        "{%0,%1,%2,%3}, {%4,%5,%6,%7}, {%8,%9}, {%0,%1,%2,%3};"
        : "+f"(d[0]), "+f"(d[1]), "+f"(d[2]), "+f"(d[3])
        : "r"(a0), "r"(a1), "r"(a2), "r"(a3), "r"(b0), "r"(b1));
}

#define CP16(dst, src) \
    asm volatile("cp.async.cg.shared.global [%0], [%1], 16;" :: "r"(dst), "l"(src))
#define CP_COMMIT() asm volatile("cp.async.commit_group;" ::: "memory")
#define CP_WAIT0()  asm volatile("cp.async.wait_group 0;" ::: "memory")

// ---- pre-packed per-lane B fragments (device globals) ---------------------
// Bf1/Bf2: tn-PAIR layout for LDS.128: idx = (s*NTP + tp)*128 + lane*4 + j.
// Bf3: (s*4+tn)*64 + lane*2 (preloaded to regs once).
__device__ uint32_t g_Bf1[13 * 8 * 32 * 2];
__device__ uint32_t g_Bf2[8 * 4 * 32 * 2];
__device__ uint32_t g_Bf3[4 * 4 * 32 * 2];

__global__ void nnue_setup(const float* __restrict__ Ww,
                           const float* __restrict__ Wb,
                           const float* __restrict__ W0,
                           const float* __restrict__ W1) {
    int t = blockIdx.x * blockDim.x + threadIdx.x;
    if (t < 6656) {   // L1: 13 steps x 4 tn-pairs x 32 lanes x 4
        int j = t & 3, lane = (t >> 2) & 31, tp = (t >> 7) & 3, s = t >> 9;
        int tn = 2 * tp + (j >> 1), e = j & 1;
        int n = 8 * tn + (lane >> 2);
        int k = 8 * s + (lane & 3) + 4 * e;
        float v = 0.0f;
        if (k < 98) {
            if (n < 32) v = Ww[n * 98 + k];
            else { int kk = k + 49; if (kk >= 98) kk -= 98; v = Wb[(n - 32) * 98 + kk]; }
        }
        g_Bf1[t] = f2tf32(v);
    }
    if (t < 2048) {   // L2: 8 steps x 2 tn-pairs x 32 lanes x 4
        int j = t & 3, lane = (t >> 2) & 31, tp = (t >> 7) & 1, s = t >> 8;
        int tn = 2 * tp + (j >> 1), e = j & 1;
        int n = 8 * tn + (lane >> 2);
        int k = 8 * s + (lane & 3) + 4 * e;
        g_Bf2[t] = f2tf32(W0[n * 64 + k]);
    }
    if (t < 1024) {   // L3
        int e = t & 1, lane = (t >> 1) & 31, tn = (t >> 6) & 3, s = t >> 8;
        int n = 8 * tn + (lane >> 2);
        int k = 8 * s + (lane & 3) + 4 * e;
        g_Bf3[t] = f2tf32(W1[n * 32 + k]);
    }
}

// ---- smem u32 offsets -----------------------------------------------------
#define U_XSZ   3136
#define U_BXSZ  2112
#define U_BX    25088
#define U_BF1   41984
#define U_BF2   48640
#define U_BF3   50688
#define U_BIAS1 51712
#define U_B0    51776
#define U_B1    51808
#define U_W2    51840
#define U_B2    51904
#define SMEM_BYTES (51908 * 4)   // ~203 KB -> 1 CTA/SM

__global__ __launch_bounds__(256, 1)
void nnue_mma(const float* __restrict__ pov,
              const float* __restrict__ white,
              const float* __restrict__ black,
              const float* __restrict__ bw,
              const float* __restrict__ bb,
              const float* __restrict__ b0,
              const float* __restrict__ b1,
              const float* __restrict__ W2,
              const float* __restrict__ b2,
              float* __restrict__ out, int ntiles) {
    extern __shared__ __align__(16) uint32_t shu[];
    float* shf = (float*)shu;
    const int t = threadIdx.x;
    const int lane = t & 31, wid = t >> 5;
    const int g = lane >> 2, q = lane & 3;
    const int r0 = wid * 32;
    const int WR = wid * U_XSZ;
    const int BXR = U_BX + wid * U_BXSZ;

    // ---- one-time: fragments + vectors + BX zero-fill ---------------------
    {
        uint4* d = (uint4*)(shu + U_BF1); const uint4* s = (const uint4*)g_Bf1;
        for (int i = t; i < 1664; i += 256) d[i] = s[i];
        d = (uint4*)(shu + U_BF2); s = (const uint4*)g_Bf2;
        for (int i = t; i < 512; i += 256) d[i] = s[i];
        d = (uint4*)(shu + U_BF3); s = (const uint4*)g_Bf3;
        for (int i = t; i < 256; i += 256) d[i] = s[i];
    }
    for (int i = t; i < 8 * U_BXSZ; i += 256) shu[U_BX + i] = 0;
    if (t < 64) shf[U_BIAS1 + t] = (t < 32) ? bw[t] : bb[t - 32];
    if (t < 64) shf[U_W2 + t]    = W2[t];
    if (t < 32) shf[U_B0 + t]    = b0[t];
    if (t < 32) shf[U_B1 + t]    = b1[t];
    if (t == 0) shf[U_B2]        = b2[0];
    __syncthreads();

    // ---- preload epi1 bias + L3 B-fragments into registers ----------------
    float blo[8], bhi[8];
#pragma unroll
    for (int i = 0; i < 8; i++) {
        int col = 8 * (i >> 1) + 2 * q + (i & 1);
        blo[i] = shf[U_BIAS1 + col];
        bhi[i] = shf[U_BIAS1 + 32 + col];
    }
    const float b2val = shf[U_B2];
    uint2 b3r[4][4];
#pragma unroll
    for (int s = 0; s < 4; s++)
#pragma unroll
        for (int tn = 0; tn < 4; tn++)
            b3r[s][tn] = *(const uint2*)&shu[U_BF3 + (s * 4 + tn) * 64 + lane * 2];

    // ---- tile-invariant bases (sigma = 4g + 2m + h) -----------------------
    const int qadj = (q > 0) ? 1519 : 0;
    int sig[2][2];
    uint32_t rbq[2][2], rbB[2][2], rbB2[2][2], rbX[2][2], rbX2[2][2];
#pragma unroll
    for (int m = 0; m < 2; m++)
#pragma unroll
        for (int h = 0; h < 2; h++) {
            int s_ = 4 * g + 2 * m + h;
            sig[m][h]  = s_;
            rbq[m][h]  = WR + s_ * 49 + q;
            rbB[m][h]  = BXR + s_ * 66;
            rbB2[m][h] = rbB[m][h] + 2 * q;
            rbX[m][h]  = BXR + s_ * 34;
            rbX2[m][h] = rbX[m][h] + 2 * q;
        }
    const int ec0 = (((2 * q) & 3) << 1) | ((2 * q) >> 2);
    const int ec1 = (((2 * q + 1) & 3) << 1) | ((2 * q + 1) >> 2);
    const uint32_t bfb1 = U_BF1 + lane * 4;
    const uint32_t bfb2 = U_BF2 + lane * 4;

    uint32_t sb;
    asm("{ .reg .u64 t; cvta.to.shared.u64 t, %1; cvt.u32.u64 %0, t; }"
        : "=r"(sb) : "l"(shu));
    const uint32_t wdst = sb + WR * 4 + lane * 16;
    const uint32_t bdst = wdst + 1568 * 4;

    // ---- staging issuers --------------------------------------------------
    auto stage_w = [&](int tile_) {
        const char* ws = (const char*)(white + ((size_t)tile_ * 256 + r0) * 49)
                         + lane * 16;
#pragma unroll
        for (int j = 0; j < 12; j++) CP16(wdst + j * 512, ws + j * 512);
        if (lane < 8) CP16(wdst + 12 * 512, ws + 12 * 512);
        CP_COMMIT();
    };
    auto stage_b = [&](int tile_) {
        const char* bs = (const char*)(black + ((size_t)tile_ * 256 + r0) * 49)
                         + lane * 16;
#pragma unroll
        for (int j = 0; j < 12; j++) CP16(bdst + j * 512, bs + j * 512);
        if (lane < 8) CP16(bdst + 12 * 512, bs + 12 * 512);
        CP_COMMIT();
    };

    // L1 A-operand loader for K-step s (s known at compile time when unrolled)
    auto load_x1 = [&](int s, uint32_t x1[2][2], uint32_t x2[2][2]) {
#pragma unroll
        for (int m = 0; m < 2; m++)
#pragma unroll
            for (int h = 0; h < 2; h++) {
                if (s < 6) {
                    x1[m][h] = shu[rbq[m][h] + 8 * s];
                    x2[m][h] = shu[rbq[m][h] + 8 * s + 4];
                } else if (s == 6) {
                    x1[m][h] = shu[rbq[m][h] + 48 + qadj];
                    x2[m][h] = shu[rbq[m][h] + 52 + 1519];
                } else {
                    x1[m][h] = shu[rbq[m][h] + 8 * s + 1519];
                    x2[m][h] = shu[rbq[m][h] + 8 * s + 4 + 1519];
                }
            }
    };

    int tile = blockIdx.x;
    if (tile < ntiles) { stage_w(tile); stage_b(tile); }

    for (; tile < ntiles; tile += gridDim.x) {
        const size_t s0 = (size_t)tile * 256;
        const int nxt = tile + gridDim.x;
        const bool hasnxt = nxt < ntiles;

        CP_WAIT0();
        __syncwarp();

        // ---- prefetch pov into regs ---------------------------------------
        float pv[2][2];
#pragma unroll
        for (int m = 0; m < 2; m++)
#pragma unroll
            for (int h = 0; h < 2; h++)
                pv[m][h] = pov[s0 + r0 + sig[m][h]];

        // ---- layer 1: D1 = X @ Wc^T, K=104; double-buffered pipeline ------
        float acc1[2][8][4];
#pragma unroll
        for (int m = 0; m < 2; m++)
#pragma unroll
            for (int tn = 0; tn < 8; tn++)
#pragma unroll
                for (int r = 0; r < 4; r++) acc1[m][tn][r] = 0.0f;

        uint32_t x1c[2][2], x2c[2][2];
        uint4 bqc[4];
        load_x1(0, x1c, x2c);
#pragma unroll
        for (int tp = 0; tp < 4; tp++)
            bqc[tp] = *(const uint4*)&shu[bfb1 + tp * 128];

#pragma unroll
        for (int s = 0; s < 13; s++) {
            uint32_t x1n[2][2], x2n[2][2];
            uint4 bqn[4];
            if (s < 12) {
                load_x1(s + 1, x1n, x2n);
#pragma unroll
                for (int tp = 0; tp < 4; tp++)
                    bqn[tp] = *(const uint4*)&shu[bfb1 + ((s + 1) * 4 + tp) * 128];
            }
#pragma unroll
            for (int tp = 0; tp < 4; tp++) {
                mma8(acc1[0][2*tp],   x1c[0][0], x1c[0][1], x2c[0][0], x2c[0][1], bqc[tp].x, bqc[tp].y);
                mma8(acc1[1][2*tp],   x1c[1][0], x1c[1][1], x2c[1][0], x2c[1][1], bqc[tp].x, bqc[tp].y);
                mma8(acc1[0][2*tp+1], x1c[0][0], x1c[0][1], x2c[0][0], x2c[0][1], bqc[tp].z, bqc[tp].w);
                mma8(acc1[1][2*tp+1], x1c[1][0], x1c[1][1], x2c[1][0], x2c[1][1], bqc[tp].z, bqc[tp].w);
            }
            if (s == 6 && hasnxt) stage_w(nxt);   // white half of X dead
            if (s < 12) {
#pragma unroll
                for (int m = 0; m < 2; m++)
#pragma unroll
                    for (int h = 0; h < 2; h++) {
                        x1c[m][h] = x1n[m][h];
                        x2c[m][h] = x2n[m][h];
                    }
#pragma unroll
                for (int tp = 0; tp < 4; tp++) bqc[tp] = bqn[tp];
            }
        }

        if (hasnxt) stage_b(nxt);   // black half of X dead

        // ---- epilogue 1: bias + pov mix + relu -> base (stride 66) --------
#pragma unroll
        for (int m = 0; m < 2; m++)
#pragma unroll
            for (int h = 0; h < 2; h++) {
                float p  = pv[m][h];
                float q1 = 1.0f - p;
#pragma unroll
                for (int tn = 0; tn < 4; tn++)
#pragma unroll
                    for (int c = 0; c < 2; c++) {
                        int i = tn * 2 + c;
                        float lo = acc1[m][tn][2 * h + c]     + blo[i];
                        float hi = acc1[m][tn + 4][2 * h + c] + bhi[i];
                        float v0 = fmaxf(p * lo + q1 * hi, 0.0f);
                        float v1 = fmaxf(p * hi + q1 * lo, 0.0f);
                        int e = (c == 0) ? ec0 : ec1;
                        shu[rbB[m][h] + tn * 8 + e]      = f2tf32(v0);
                        shu[rbB[m][h] + tn * 8 + e + 32] = f2tf32(v1);
                    }
            }
        __syncwarp();

        // ---- layer 2: D2 = base @ W0^T, K=64; double-buffered -------------
        float acc2[2][4][4];
#pragma unroll
        for (int m = 0; m < 2; m++)
#pragma unroll
            for (int tn = 0; tn < 4; tn++)
#pragma unroll
                for (int r = 0; r < 4; r++) acc2[m][tn][r] = 0.0f;

        uint2 avc[2][2];
        uint4 bq2c[2];
#pragma unroll
        for (int m = 0; m < 2; m++)
#pragma unroll
            for (int h = 0; h < 2; h++)
                avc[m][h] = *(const uint2*)&shu[rbB2[m][h]];
#pragma unroll
        for (int tp = 0; tp < 2; tp++)
            bq2c[tp] = *(const uint4*)&shu[bfb2 + tp * 128];

#pragma unroll
        for (int s = 0; s < 8; s++) {
            uint2 avn[2][2];
            uint4 bq2n[2];
            if (s < 7) {
#pragma unroll
                for (int m = 0; m < 2; m++)
#pragma unroll
                    for (int h = 0; h < 2; h++)
                        avn[m][h] = *(const uint2*)&shu[rbB2[m][h] + (s + 1) * 8];
#pragma unroll
                for (int tp = 0; tp < 2; tp++)
                    bq2n[tp] = *(const uint4*)&shu[bfb2 + ((s + 1) * 2 + tp) * 128];
            }
#pragma unroll
            for (int tp = 0; tp < 2; tp++) {
                mma8(acc2[0][2*tp],   avc[0][0].x, avc[0][1].x, avc[0][0].y, avc[0][1].y, bq2c[tp].x, bq2c[tp].y);
                mma8(acc2[1][2*tp],   avc[1][0].x, avc[1][1].x, avc[1][0].y, avc[1][1].y, bq2c[tp].x, bq2c[tp].y);
                mma8(acc2[0][2*tp+1], avc[0][0].x, avc[0][1].x, avc[0][0].y, avc[0][1].y, bq2c[tp].z, bq2c[tp].w);
                mma8(acc2[1][2*tp+1], avc[1][0].x, avc[1][1].x, avc[1][0].y, avc[1][1].y, bq2c[tp].z, bq2c[tp].w);
            }
            if (s < 7) {
#pragma unroll
                for (int m = 0; m < 2; m++)
#pragma unroll
                    for (int h = 0; h < 2; h++) avc[m][h] = avn[m][h];
#pragma unroll
                for (int tp = 0; tp < 2; tp++) bq2c[tp] = bq2n[tp];
            }
        }
        __syncwarp();

        // ---- epilogue 2: x0 = relu(D2+b0) -> stride 34; W2[0:32] dot ------
        float dot[2][2] = {{0.0f, 0.0f}, {0.0f, 0.0f}};
#pragma unroll
        for (int m = 0; m < 2; m++)
#pragma unroll
            for (int h = 0; h < 2; h++)
#pragma unroll
                for (int tn = 0; tn < 4; tn++)
#pragma unroll
                    for (int c = 0; c < 2; c++) {
                        int col = 8 * tn + 2 * q + c;
                        float v = fmaxf(acc2[m][tn][2 * h + c] + shf[U_B0 + col], 0.0f);
                        dot[m][h] += v * shf[U_W2 + col];
                        int e = (c == 0) ? ec0 : ec1;
                        shu[rbX[m][h] + tn * 8 + e] = f2tf32(v);
                    }
        __syncwarp();

        // ---- layer 3: D3 = x0 @ W1^T, K=32 (B-frags in regs) --------------
        float acc3[2][4][4];
#pragma unroll
        for (int m = 0; m < 2; m++)
#pragma unroll
            for (int tn = 0; tn < 4; tn++)
#pragma unroll
                for (int r = 0; r < 4; r++) acc3[m][tn][r] = 0.0f;

#pragma unroll
        for (int s = 0; s < 4; s++) {
            uint2 av[2][2];
#pragma unroll
            for (int m = 0; m < 2; m++)
#pragma unroll
                for (int h = 0; h < 2; h++)
                    av[m][h] = *(const uint2*)&shu[rbX2[m][h] + s * 8];
#pragma unroll
            for (int tn = 0; tn < 4; tn++) {
                mma8(acc3[0][tn], av[0][0].x, av[0][1].x, av[0][0].y, av[0][1].y,
                     b3r[s][tn].x, b3r[s][tn].y);
                mma8(acc3[1][tn], av[1][0].x, av[1][1].x, av[1][0].y, av[1][1].y,
                     b3r[s][tn].x, b3r[s][tn].y);
            }
        }

        // ---- epilogue 3: dot += relu(D3+b1).W2[32:]; reduce; store --------
#pragma unroll
        for (int m = 0; m < 2; m++)
#pragma unroll
            for (int h = 0; h < 2; h++) {
#pragma unroll
                for (int tn = 0; tn < 4; tn++)
#pragma unroll
                    for (int c = 0; c < 2; c++) {
                        int col = 8 * tn + 2 * q + c;
                        float v = fmaxf(acc3[m][tn][2 * h + c] + shf[U_B1 + col], 0.0f);
                        dot[m][h] += v * shf[U_W2 + 32 + col];
                    }
                float d = dot[m][h];
                d += __shfl_xor_sync(0xffffffffu, d, 1);
                d += __shfl_xor_sync(0xffffffffu, d, 2);
                if (q == 0)
                    out[s0 + r0 + sig[m][h]] = d + b2val;
            }
        __syncwarp();
    }
}

// ---------------------------------------------------------------------------
extern "C" void kernel_launch(void* const* d_in, const int* in_sizes, int n_in,
                              void* d_out, int out_size) {
    const float* pov   = (const float*)d_in[0];
    const float* white = (const float*)d_in[1];
    const float* black = (const float*)d_in[2];
    const float* Ww    = (const float*)d_in[3];
    const float* bw    = (const float*)d_in[4];
    const float* Wb    = (const float*)d_in[5];
    const float* bb    = (const float*)d_in[6];
    const float* W0    = (const float*)d_in[7];
    const float* b0    = (const float*)d_in[8];
    const float* W1    = (const float*)d_in[9];
    const float* b1    = (const float*)d_in[10];
    const float* W2    = (const float*)d_in[11];
    const float* b2    = (const float*)d_in[12];

    const int B = in_sizes[0];
    const int ntiles = B / 256;

    cudaFuncSetAttribute(nnue_mma,
                         cudaFuncAttributeMaxDynamicSharedMemorySize, SMEM_BYTES);

    nnue_setup<<<26, 256>>>(Ww, Wb, W0, W1);
    nnue_mma<<<148, 256, SMEM_BYTES>>>(pov, white, black, bw, bb,
                                       b0, b1, W2, b2, (float*)d_out, ntiles);
}

// round 17
// speedup vs baseline: 1.1384x; 1.1384x over previous
#include <cuda_runtime.h>
#include <cstdint>

// ===========================================================================
// NNUE eval via tensor-core mma.sync (tf32, m16n8k8), compute_103-safe PTX.
// R17 = R14 (proven 129.8us champion) + SPLIT cp.async wait:
//   tile top: wait_group 1  (white complete; black may still fly)
//   before K-step 6: wait_group 0 (black needed from s=6 on)
// All else identical to R14: 148 CTAs x 256 thr, warp-private 32 samples,
// BX overlay region, stage_w@s6 / stage_b post-L1 prefetch of next tile,
// LDS.128-packed B1/B2 fragments, L3 B-frags + bias/W2 vectors in regs.
// ===========================================================================

__device__ __forceinline__ uint32_t f2tf32(float f) {
    uint32_t r; asm("cvt.rna.tf32.f32 %0, %1;" : "=r"(r) : "f"(f)); return r;
}

__device__ __forceinline__ void mma8(float* d,
                                     uint32_t a0, uint32_t a1, uint32_t a2, uint32_t a3,
                                     uint32_t b0, uint32_t b1) {
    asm volatile(
        "mma.sync.aligned.m16n8k8.row.col.f32.tf32.tf32.f32 "
        "{%0,%1,%2,%3}, {%4,%5,%6,%7}, {%8,%9}, {%0,%1,%2,%3};"
        : "+f"(d[0]), "+f"(d[1]), "+f"(d[2]), "+f"(d[3])
        : "r"(a0), "r"(a1), "r"(a2), "r"(a3), "r"(b0), "r"(b1));
}

#define CP16(dst, src) \
    asm volatile("cp.async.cg.shared.global [%0], [%1], 16;" :: "r"(dst), "l"(src))
#define CP_COMMIT() asm volatile("cp.async.commit_group;" ::: "memory")
#define CP_WAIT0()  asm volatile("cp.async.wait_group 0;" ::: "memory")
#define CP_WAIT1()  asm volatile("cp.async.wait_group 1;" ::: "memory")

// ---- pre-packed per-lane B fragments (device globals) ---------------------
// Bf1/Bf2: tn-PAIR layout for LDS.128: idx = (s*NTP + tp)*128 + lane*4 + j.
// Bf3: (s*4+tn)*64 + lane*2 (preloaded to regs once).
__device__ uint32_t g_Bf1[13 * 8 * 32 * 2];
__device__ uint32_t g_Bf2[8 * 4 * 32 * 2];
__device__ uint32_t g_Bf3[4 * 4 * 32 * 2];

__global__ void nnue_setup(const float* __restrict__ Ww,
                           const float* __restrict__ Wb,
                           const float* __restrict__ W0,
                           const float* __restrict__ W1) {
    int t = blockIdx.x * blockDim.x + threadIdx.x;
    if (t < 6656) {   // L1: 13 steps x 4 tn-pairs x 32 lanes x 4
        int j = t & 3, lane = (t >> 2) & 31, tp = (t >> 7) & 3, s = t >> 9;
        int tn = 2 * tp + (j >> 1), e = j & 1;
        int n = 8 * tn + (lane >> 2);
        int k = 8 * s + (lane & 3) + 4 * e;
        float v = 0.0f;
        if (k < 98) {
            if (n < 32) v = Ww[n * 98 + k];
            else { int kk = k + 49; if (kk >= 98) kk -= 98; v = Wb[(n - 32) * 98 + kk]; }
        }
        g_Bf1[t] = f2tf32(v);
    }
    if (t < 2048) {   // L2: 8 steps x 2 tn-pairs x 32 lanes x 4
        int j = t & 3, lane = (t >> 2) & 31, tp = (t >> 7) & 1, s = t >> 8;
        int tn = 2 * tp + (j >> 1), e = j & 1;
        int n = 8 * tn + (lane >> 2);
        int k = 8 * s + (lane & 3) + 4 * e;
        g_Bf2[t] = f2tf32(W0[n * 64 + k]);
    }
    if (t < 1024) {   // L3
        int e = t & 1, lane = (t >> 1) & 31, tn = (t >> 6) & 3, s = t >> 8;
        int n = 8 * tn + (lane >> 2);
        int k = 8 * s + (lane & 3) + 4 * e;
        g_Bf3[t] = f2tf32(W1[n * 32 + k]);
    }
}

// ---- smem u32 offsets -----------------------------------------------------
#define U_XSZ   3136
#define U_BXSZ  2112
#define U_BX    25088
#define U_BF1   41984
#define U_BF2   48640
#define U_BF3   50688
#define U_BIAS1 51712
#define U_B0    51776
#define U_B1    51808
#define U_W2    51840
#define U_B2    51904
#define SMEM_BYTES (51908 * 4)   // ~203 KB -> 1 CTA/SM

__global__ __launch_bounds__(256, 1)
void nnue_mma(const float* __restrict__ pov,
              const float* __restrict__ white,
              const float* __restrict__ black,
              const float* __restrict__ bw,
              const float* __restrict__ bb,
              const float* __restrict__ b0,
              const float* __restrict__ b1,
              const float* __restrict__ W2,
              const float* __restrict__ b2,
              float* __restrict__ out, int ntiles) {
    extern __shared__ __align__(16) uint32_t shu[];
    float* shf = (float*)shu;
    const int t = threadIdx.x;
    const int lane = t & 31, wid = t >> 5;
    const int g = lane >> 2, q = lane & 3;
    const int r0 = wid * 32;
    const int WR = wid * U_XSZ;
    const int BXR = U_BX + wid * U_BXSZ;

    // ---- one-time: fragments + vectors + BX zero-fill ---------------------
    {
        uint4* d = (uint4*)(shu + U_BF1); const uint4* s = (const uint4*)g_Bf1;
        for (int i = t; i < 1664; i += 256) d[i] = s[i];
        d = (uint4*)(shu + U_BF2); s = (const uint4*)g_Bf2;
        for (int i = t; i < 512; i += 256) d[i] = s[i];
        d = (uint4*)(shu + U_BF3); s = (const uint4*)g_Bf3;
        for (int i = t; i < 256; i += 256) d[i] = s[i];
    }
    for (int i = t; i < 8 * U_BXSZ; i += 256) shu[U_BX + i] = 0;
    if (t < 64) shf[U_BIAS1 + t] = (t < 32) ? bw[t] : bb[t - 32];
    if (t < 64) shf[U_W2 + t]    = W2[t];
    if (t < 32) shf[U_B0 + t]    = b0[t];
    if (t < 32) shf[U_B1 + t]    = b1[t];
    if (t == 0) shf[U_B2]        = b2[0];
    __syncthreads();

    // ---- preload per-thread vectors + L3 B-fragments into registers -------
    float blo[8], bhi[8], b0r[8], b1r[8], w2lo[8], w2hi[8];
#pragma unroll
    for (int i = 0; i < 8; i++) {
        int col = 8 * (i >> 1) + 2 * q + (i & 1);
        blo[i]  = shf[U_BIAS1 + col];
        bhi[i]  = shf[U_BIAS1 + 32 + col];
        b0r[i]  = shf[U_B0 + col];
        b1r[i]  = shf[U_B1 + col];
        w2lo[i] = shf[U_W2 + col];
        w2hi[i] = shf[U_W2 + 32 + col];
    }
    const float b2val = shf[U_B2];
    uint2 b3r[4][4];
#pragma unroll
    for (int s = 0; s < 4; s++)
#pragma unroll
        for (int tn = 0; tn < 4; tn++)
            b3r[s][tn] = *(const uint2*)&shu[U_BF3 + (s * 4 + tn) * 64 + lane * 2];

    // ---- tile-invariant bases (sigma = 4g + 2m + h) -----------------------
    const int qadj = (q > 0) ? 1519 : 0;
    int sig[2][2];
    uint32_t rbq[2][2], rbB[2][2], rbB2[2][2], rbX[2][2], rbX2[2][2];
#pragma unroll
    for (int m = 0; m < 2; m++)
#pragma unroll
        for (int h = 0; h < 2; h++) {
            int s_ = 4 * g + 2 * m + h;
            sig[m][h]  = s_;
            rbq[m][h]  = WR + s_ * 49 + q;
            rbB[m][h]  = BXR + s_ * 66;
            rbB2[m][h] = rbB[m][h] + 2 * q;
            rbX[m][h]  = BXR + s_ * 34;
            rbX2[m][h] = rbX[m][h] + 2 * q;
        }
    const int ec0 = (((2 * q) & 3) << 1) | ((2 * q) >> 2);
    const int ec1 = (((2 * q + 1) & 3) << 1) | ((2 * q + 1) >> 2);
    const uint32_t bfb1 = U_BF1 + lane * 4;
    const uint32_t bfb2 = U_BF2 + lane * 4;

    uint32_t sb;
    asm("{ .reg .u64 t; cvta.to.shared.u64 t, %1; cvt.u32.u64 %0, t; }"
        : "=r"(sb) : "l"(shu));
    const uint32_t wdst = sb + WR * 4 + lane * 16;
    const uint32_t bdst = wdst + 1568 * 4;

    // ---- staging issuers (separate commit groups: white first, black) -----
    auto stage_w = [&](int tile_) {
        const char* ws = (const char*)(white + ((size_t)tile_ * 256 + r0) * 49)
                         + lane * 16;
#pragma unroll
        for (int j = 0; j < 12; j++) CP16(wdst + j * 512, ws + j * 512);
        if (lane < 8) CP16(wdst + 12 * 512, ws + 12 * 512);
        CP_COMMIT();
    };
    auto stage_b = [&](int tile_) {
        const char* bs = (const char*)(black + ((size_t)tile_ * 256 + r0) * 49)
                         + lane * 16;
#pragma unroll
        for (int j = 0; j < 12; j++) CP16(bdst + j * 512, bs + j * 512);
        if (lane < 8) CP16(bdst + 12 * 512, bs + 12 * 512);
        CP_COMMIT();
    };

    int tile = blockIdx.x;
    if (tile < ntiles) { stage_w(tile); stage_b(tile); }

    for (; tile < ntiles; tile += gridDim.x) {
        const size_t s0 = (size_t)tile * 256;
        const int nxt = tile + gridDim.x;
        const bool hasnxt = nxt < ntiles;

        // white group (committed first) complete; black may still be in flight
        CP_WAIT1();
        __syncwarp();

        // ---- prefetch pov into regs (consumed in epi1) --------------------
        float pv[2][2];
#pragma unroll
        for (int m = 0; m < 2; m++)
#pragma unroll
            for (int h = 0; h < 2; h++)
                pv[m][h] = pov[s0 + r0 + sig[m][h]];

        // ---- layer 1: D1 = X @ Wc^T, K=104 (13 steps) ---------------------
        float acc1[2][8][4];
#pragma unroll
        for (int m = 0; m < 2; m++)
#pragma unroll
            for (int tn = 0; tn < 8; tn++)
#pragma unroll
                for (int r = 0; r < 4; r++) acc1[m][tn][r] = 0.0f;

        // steps 0..5: white region only (black still arriving)
#pragma unroll
        for (int s = 0; s < 6; s++) {
            uint32_t x1[2][2], x2[2][2];
#pragma unroll
            for (int m = 0; m < 2; m++)
#pragma unroll
                for (int h = 0; h < 2; h++) {
                    x1[m][h] = shu[rbq[m][h] + 8 * s];
                    x2[m][h] = shu[rbq[m][h] + 8 * s + 4];
                }
#pragma unroll
            for (int tp = 0; tp < 4; tp++) {
                uint4 bq = *(const uint4*)&shu[bfb1 + (s * 4 + tp) * 128];
                mma8(acc1[0][2*tp],   x1[0][0], x1[0][1], x2[0][0], x2[0][1], bq.x, bq.y);
                mma8(acc1[1][2*tp],   x1[1][0], x1[1][1], x2[1][0], x2[1][1], bq.x, bq.y);
                mma8(acc1[0][2*tp+1], x1[0][0], x1[0][1], x2[0][0], x2[0][1], bq.z, bq.w);
                mma8(acc1[1][2*tp+1], x1[1][0], x1[1][1], x2[1][0], x2[1][1], bq.z, bq.w);
            }
        }

        // black group must be complete from step 6 on
        CP_WAIT0();
        __syncwarp();

        // step 6 (white/black straddle)
        {
            uint32_t x1[2][2], x2[2][2];
#pragma unroll
            for (int m = 0; m < 2; m++)
#pragma unroll
                for (int h = 0; h < 2; h++) {
                    x1[m][h] = shu[rbq[m][h] + 48 + qadj];
                    x2[m][h] = shu[rbq[m][h] + 52 + 1519];
                }
#pragma unroll
            for (int tp = 0; tp < 4; tp++) {
                uint4 bq = *(const uint4*)&shu[bfb1 + (6 * 4 + tp) * 128];
                mma8(acc1[0][2*tp],   x1[0][0], x1[0][1], x2[0][0], x2[0][1], bq.x, bq.y);
                mma8(acc1[1][2*tp],   x1[1][0], x1[1][1], x2[1][0], x2[1][1], bq.x, bq.y);
                mma8(acc1[0][2*tp+1], x1[0][0], x1[0][1], x2[0][0], x2[0][1], bq.z, bq.w);
                mma8(acc1[1][2*tp+1], x1[1][0], x1[1][1], x2[1][0], x2[1][1], bq.z, bq.w);
            }
        }

        // white half of X is dead -> prefetch next tile's white NOW
        if (hasnxt) stage_w(nxt);

        // steps 7..12 (black region only)
#pragma unroll
        for (int s = 7; s < 13; s++) {
            uint32_t x1[2][2], x2[2][2];
#pragma unroll
            for (int m = 0; m < 2; m++)
#pragma unroll
                for (int h = 0; h < 2; h++) {
                    x1[m][h] = shu[rbq[m][h] + 8 * s + 1519];
                    x2[m][h] = shu[rbq[m][h] + 8 * s + 4 + 1519];
                }
#pragma unroll
            for (int tp = 0; tp < 4; tp++) {
                uint4 bq = *(const uint4*)&shu[bfb1 + (s * 4 + tp) * 128];
                mma8(acc1[0][2*tp],   x1[0][0], x1[0][1], x2[0][0], x2[0][1], bq.x, bq.y);
                mma8(acc1[1][2*tp],   x1[1][0], x1[1][1], x2[1][0], x2[1][1], bq.x, bq.y);
                mma8(acc1[0][2*tp+1], x1[0][0], x1[0][1], x2[0][0], x2[0][1], bq.z, bq.w);
                mma8(acc1[1][2*tp+1], x1[1][0], x1[1][1], x2[1][0], x2[1][1], bq.z, bq.w);
            }
        }

        // black half of X is dead -> prefetch next tile's black
        if (hasnxt) stage_b(nxt);

        // ---- epilogue 1: bias + pov mix + relu -> base (stride 66) --------
#pragma unroll
        for (int m = 0; m < 2; m++)
#pragma unroll
            for (int h = 0; h < 2; h++) {
                float p  = pv[m][h];
                float q1 = 1.0f - p;
#pragma unroll
                for (int tn = 0; tn < 4; tn++)
#pragma unroll
                    for (int c = 0; c < 2; c++) {
                        int i = tn * 2 + c;
                        float lo = acc1[m][tn][2 * h + c]     + blo[i];
                        float hi = acc1[m][tn + 4][2 * h + c] + bhi[i];
                        float v0 = fmaxf(p * lo + q1 * hi, 0.0f);
                        float v1 = fmaxf(p * hi + q1 * lo, 0.0f);
                        int e = (c == 0) ? ec0 : ec1;
                        shu[rbB[m][h] + tn * 8 + e]      = f2tf32(v0);
                        shu[rbB[m][h] + tn * 8 + e + 32] = f2tf32(v1);
                    }
            }
        __syncwarp();

        // ---- layer 2: D2 = base @ W0^T, K=64 ------------------------------
        float acc2[2][4][4];
#pragma unroll
        for (int m = 0; m < 2; m++)
#pragma unroll
            for (int tn = 0; tn < 4; tn++)
#pragma unroll
                for (int r = 0; r < 4; r++) acc2[m][tn][r] = 0.0f;

#pragma unroll
        for (int s = 0; s < 8; s++) {
            uint2 av[2][2];
#pragma unroll
            for (int m = 0; m < 2; m++)
#pragma unroll
                for (int h = 0; h < 2; h++)
                    av[m][h] = *(const uint2*)&shu[rbB2[m][h] + s * 8];
#pragma unroll
            for (int tp = 0; tp < 2; tp++) {
                uint4 bq = *(const uint4*)&shu[bfb2 + (s * 2 + tp) * 128];
                mma8(acc2[0][2*tp],   av[0][0].x, av[0][1].x, av[0][0].y, av[0][1].y, bq.x, bq.y);
                mma8(acc2[1][2*tp],   av[1][0].x, av[1][1].x, av[1][0].y, av[1][1].y, bq.x, bq.y);
                mma8(acc2[0][2*tp+1], av[0][0].x, av[0][1].x, av[0][0].y, av[0][1].y, bq.z, bq.w);
                mma8(acc2[1][2*tp+1], av[1][0].x, av[1][1].x, av[1][0].y, av[1][1].y, bq.z, bq.w);
            }
        }
        __syncwarp();

        // ---- epilogue 2: x0 = relu(D2+b0) -> stride 34; W2[0:32] dot ------
        float dot[2][2] = {{0.0f, 0.0f}, {0.0f, 0.0f}};
#pragma unroll
        for (int m = 0; m < 2; m++)
#pragma unroll
            for (int h = 0; h < 2; h++)
#pragma unroll
                for (int tn = 0; tn < 4; tn++)
#pragma unroll
                    for (int c = 0; c < 2; c++) {
                        int i = tn * 2 + c;
                        float v = fmaxf(acc2[m][tn][2 * h + c] + b0r[i], 0.0f);
                        dot[m][h] += v * w2lo[i];
                        int e = (c == 0) ? ec0 : ec1;
                        shu[rbX[m][h] + tn * 8 + e] = f2tf32(v);
                    }
        __syncwarp();

        // ---- layer 3: D3 = x0 @ W1^T, K=32 (B-frags in regs) --------------
        float acc3[2][4][4];
#pragma unroll
        for (int m = 0; m < 2; m++)
#pragma unroll
            for (int tn = 0; tn < 4; tn++)
#pragma unroll
                for (int r = 0; r < 4; r++) acc3[m][tn][r] = 0.0f;

#pragma unroll
        for (int s = 0; s < 4; s++) {
            uint2 av[2][2];
#pragma unroll
            for (int m = 0; m < 2; m++)
#pragma unroll
                for (int h = 0; h < 2; h++)
                    av[m][h] = *(const uint2*)&shu[rbX2[m][h] + s * 8];
#pragma unroll
            for (int tn = 0; tn < 4; tn++) {
                mma8(acc3[0][tn], av[0][0].x, av[0][1].x, av[0][0].y, av[0][1].y,
                     b3r[s][tn].x, b3r[s][tn].y);
                mma8(acc3[1][tn], av[1][0].x, av[1][1].x, av[1][0].y, av[1][1].y,
                     b3r[s][tn].x, b3r[s][tn].y);
            }
        }

        // ---- epilogue 3: dot += relu(D3+b1).W2[32:]; reduce; store --------
#pragma unroll
        for (int m = 0; m < 2; m++)
#pragma unroll
            for (int h = 0; h < 2; h++) {
#pragma unroll
                for (int tn = 0; tn < 4; tn++)
#pragma unroll
                    for (int c = 0; c < 2; c++) {
                        int i = tn * 2 + c;
                        float v = fmaxf(acc3[m][tn][2 * h + c] + b1r[i], 0.0f);
                        dot[m][h] += v * w2hi[i];
                    }
                float d = dot[m][h];
                d += __shfl_xor_sync(0xffffffffu, d, 1);
                d += __shfl_xor_sync(0xffffffffu, d, 2);
                if (q == 0)
                    out[s0 + r0 + sig[m][h]] = d + b2val;
            }
        __syncwarp();
    }
}

// ---------------------------------------------------------------------------
extern "C" void kernel_launch(void* const* d_in, const int* in_sizes, int n_in,
                              void* d_out, int out_size) {
    const float* pov   = (const float*)d_in[0];
    const float* white = (const float*)d_in[1];
    const float* black = (const float*)d_in[2];
    const float* Ww    = (const float*)d_in[3];
    const float* bw    = (const float*)d_in[4];
    const float* Wb    = (const float*)d_in[5];
    const float* bb    = (const float*)d_in[6];
    const float* W0    = (const float*)d_in[7];
    const float* b0    = (const float*)d_in[8];
    const float* W1    = (const float*)d_in[9];
    const float* b1    = (const float*)d_in[10];
    const float* W2    = (const float*)d_in[11];
    const float* b2    = (const float*)d_in[12];

    const int B = in_sizes[0];
    const int ntiles = B / 256;

    cudaFuncSetAttribute(nnue_mma,
                         cudaFuncAttributeMaxDynamicSharedMemorySize, SMEM_BYTES);

    nnue_setup<<<26, 256>>>(Ww, Wb, W0, W1);
    nnue_mma<<<148, 256, SMEM_BYTES>>>(pov, white, black, bw, bb,
                                       b0, b1, W2, b2, (float*)d_out, ntiles);
}